// round 16
// baseline (speedup 1.0000x reference)
#include <cuda_runtime.h>
#include <cuda_fp16.h>
#include <cstdint>

#define N_NODES 10000
#define N_EDGES_MAX 160000
#define D_IN    512
#define D_HID   1024
#define CAP     128

// ---------------- scratch (__device__ globals; no allocs) ------------------
__device__ __half g_feat_h[N_NODES * D_IN];
__device__ __half g_rst_h[N_NODES * D_IN];
__device__ __half g_h[N_NODES * D_HID];
__device__ __half g_w1t[D_IN * D_HID];       // W1^T fp16 [1024, 512]
__device__ __half g_w2t[D_HID * D_IN];       // W2^T fp16 [512, 1024]
__device__ int    g_cnt[N_NODES];
__device__ int    g_eidx[N_NODES * CAP];

// ---------------- helpers --------------------------------------------------
__device__ __forceinline__ uint32_t smem_u32(const void* p) {
    uint32_t a;
    asm("{ .reg .u64 t; cvta.to.shared.u64 t, %1; cvt.u32.u64 %0, t; }"
        : "=r"(a) : "l"(p));
    return a;
}
__device__ __forceinline__ void cp_async16(uint32_t dst, const void* src, uint32_t bytes) {
    asm volatile("cp.async.ca.shared.global [%0], [%1], 16, %2;"
                 :: "r"(dst), "l"(src), "r"(bytes) : "memory");
}
#define CP_COMMIT() asm volatile("cp.async.commit_group;" ::: "memory")
#define CP_WAIT2()  asm volatile("cp.async.wait_group 2;" ::: "memory")

__device__ __forceinline__ void acc_u4(float* a, uint4 u) {
    const __half2* hp = reinterpret_cast<const __half2*>(&u);
#pragma unroll
    for (int q = 0; q < 4; q++) {
        float2 f = __half22float2(hp[q]);
        a[q * 2 + 0] += f.x;
        a[q * 2 + 1] += f.y;
    }
}

// ---------------------------------------------------------------------------
// Fused prep kernel (one launch)
// ---------------------------------------------------------------------------
#define NB_CVT  2500
#define NB_T1   512
#define NB_T2   512
#define NB_ZERO 40
#define NB_PREP (NB_CVT + NB_T1 + NB_T2 + NB_ZERO)

__device__ __forceinline__ void do_transpose(const float* __restrict__ W,
                                             __half* __restrict__ WT,
                                             int K, int N, int bx, int by,
                                             int tx, int ty) {
    __shared__ float t[32][33];
    int n0 = bx * 32, k0 = by * 32;
#pragma unroll
    for (int j = 0; j < 4; j++)
        t[ty + j * 8][tx] = W[(size_t)(k0 + ty + j * 8) * N + n0 + tx];
    __syncthreads();
#pragma unroll
    for (int j = 0; j < 4; j++)
        WT[(size_t)(n0 + ty + j * 8) * K + k0 + tx] = __float2half_rn(t[tx][ty + j * 8]);
}

__global__ __launch_bounds__(256)
void prep_kernel(const float* __restrict__ feat,
                 const float* __restrict__ W1, const float* __restrict__ W2,
                 __half* __restrict__ feath, __half* __restrict__ w1t,
                 __half* __restrict__ w2t, int* __restrict__ cnt) {
    int b = blockIdx.x;
    int tid = threadIdx.x;
    if (b < NB_CVT) {
        int i = b * 256 + tid;
        float4 a = reinterpret_cast<const float4*>(feat)[i * 2];
        float4 c = reinterpret_cast<const float4*>(feat)[i * 2 + 1];
        __half2 h0 = __floats2half2_rn(a.x, a.y);
        __half2 h1 = __floats2half2_rn(a.z, a.w);
        __half2 h2 = __floats2half2_rn(c.x, c.y);
        __half2 h3 = __floats2half2_rn(c.z, c.w);
        uint4 t;
        t.x = *reinterpret_cast<uint32_t*>(&h0);
        t.y = *reinterpret_cast<uint32_t*>(&h1);
        t.z = *reinterpret_cast<uint32_t*>(&h2);
        t.w = *reinterpret_cast<uint32_t*>(&h3);
        reinterpret_cast<uint4*>(feath)[i] = t;
    } else if (b < NB_CVT + NB_T1) {
        int bb = b - NB_CVT;
        do_transpose(W1, w1t, D_IN, D_HID, bb & 31, bb >> 5, tid & 31, tid >> 5);
    } else if (b < NB_CVT + NB_T1 + NB_T2) {
        int bb = b - NB_CVT - NB_T1;
        do_transpose(W2, w2t, D_HID, D_IN, bb & 15, bb >> 4, tid & 31, tid >> 5);
    } else {
        int bb = b - NB_CVT - NB_T1 - NB_T2;
        int i = bb * 256 + tid;
        if (i < N_NODES) cnt[i] = 0;
    }
}

// ---------------------------------------------------------------------------
// Bucketed adjacency fill
// ---------------------------------------------------------------------------
__global__ void fill_kernel(const int* __restrict__ src, const int* __restrict__ dst,
                            int* __restrict__ cnt, int* __restrict__ eidx,
                            int n_edges) {
    int base = (blockIdx.x * blockDim.x + threadIdx.x) * 4;
#pragma unroll
    for (int j = 0; j < 4; j++) {
        int i = base + j;
        if (i < n_edges) {
            int d = dst[i];
            int pos = atomicAdd(&cnt[d], 1);
            eidx[d * CAP + pos] = src[i];
        }
    }
}

// ---------------------------------------------------------------------------
// Fused gather (fp16 feat): one warp per dst node, 4 neighbors in flight.
// ---------------------------------------------------------------------------
__global__ __launch_bounds__(256)
void gather_kernel(const __half* __restrict__ feath, const float* __restrict__ eps,
                   const int* __restrict__ cnt, const int* __restrict__ eidx,
                   __half* __restrict__ rsth) {
    int node = (blockIdx.x * blockDim.x + threadIdx.x) >> 5;
    int lane = threadIdx.x & 31;
    if (node >= N_NODES) return;

    float acc[16];
    {
        float s = 1.0f + eps[0];
        const uint4* fd = reinterpret_cast<const uint4*>(feath + (size_t)node * D_IN);
#pragma unroll
        for (int i = 0; i < 2; i++) {
            uint4 u = fd[lane + i * 32];
            const __half2* hp = reinterpret_cast<const __half2*>(&u);
#pragma unroll
            for (int q = 0; q < 4; q++) {
                float2 f = __half22float2(hp[q]);
                acc[i * 8 + q * 2 + 0] = s * f.x;
                acc[i * 8 + q * 2 + 1] = s * f.y;
            }
        }
    }
    const int deg = cnt[node];
    const int* ep = eidx + (size_t)node * CAP;
    for (int j0 = 0; j0 < deg; j0 += 32) {
        int mine = (j0 + lane < deg) ? ep[j0 + lane] : 0;
        int m = deg - j0; if (m > 32) m = 32;
        int jj = 0;
        for (; jj + 4 <= m; jj += 4) {
            int s0 = __shfl_sync(0xFFFFFFFFu, mine, jj + 0);
            int s1 = __shfl_sync(0xFFFFFFFFu, mine, jj + 1);
            int s2 = __shfl_sync(0xFFFFFFFFu, mine, jj + 2);
            int s3 = __shfl_sync(0xFFFFFFFFu, mine, jj + 3);
            const uint4* f0 = reinterpret_cast<const uint4*>(feath + (size_t)s0 * D_IN);
            const uint4* f1 = reinterpret_cast<const uint4*>(feath + (size_t)s1 * D_IN);
            const uint4* f2 = reinterpret_cast<const uint4*>(feath + (size_t)s2 * D_IN);
            const uint4* f3 = reinterpret_cast<const uint4*>(feath + (size_t)s3 * D_IN);
            uint4 u0a = f0[lane], u0b = f0[lane + 32];
            uint4 u1a = f1[lane], u1b = f1[lane + 32];
            uint4 u2a = f2[lane], u2b = f2[lane + 32];
            uint4 u3a = f3[lane], u3b = f3[lane + 32];
            acc_u4(acc, u0a); acc_u4(acc + 8, u0b);
            acc_u4(acc, u1a); acc_u4(acc + 8, u1b);
            acc_u4(acc, u2a); acc_u4(acc + 8, u2b);
            acc_u4(acc, u3a); acc_u4(acc + 8, u3b);
        }
        for (; jj < m; jj++) {
            int s = __shfl_sync(0xFFFFFFFFu, mine, jj);
            const uint4* fs = reinterpret_cast<const uint4*>(feath + (size_t)s * D_IN);
            uint4 ua = fs[lane], ub = fs[lane + 32];
            acc_u4(acc, ua); acc_u4(acc + 8, ub);
        }
    }
    uint4* ro = reinterpret_cast<uint4*>(rsth + (size_t)node * D_IN);
#pragma unroll
    for (int i = 0; i < 2; i++) {
        __half2 h0 = __floats2half2_rn(acc[i * 8 + 0], acc[i * 8 + 1]);
        __half2 h1 = __floats2half2_rn(acc[i * 8 + 2], acc[i * 8 + 3]);
        __half2 h2 = __floats2half2_rn(acc[i * 8 + 4], acc[i * 8 + 5]);
        __half2 h3 = __floats2half2_rn(acc[i * 8 + 6], acc[i * 8 + 7]);
        uint4 t;
        t.x = *reinterpret_cast<uint32_t*>(&h0);
        t.y = *reinterpret_cast<uint32_t*>(&h1);
        t.z = *reinterpret_cast<uint32_t*>(&h2);
        t.w = *reinterpret_cast<uint32_t*>(&h3);
        ro[lane + i * 32] = t;
    }
}

// ---------------------------------------------------------------------------
// FP16 mma.sync GEMM, 4-stage cp.async pipeline, register-double-buffered
// ldmatrix fragments, one __syncthreads per K-chunk, 1 CTA/SM (reg-rich).
// ---------------------------------------------------------------------------
#define TILE_B 16384
#define STAGE_BYTES (2 * TILE_B)
#define NSTAGE 4
#define GSM_TOTAL (NSTAGE * STAGE_BYTES)

template <bool RELU, bool RESID, bool OUT_HALF>
__global__ __launch_bounds__(256, 1)
void gemm_fp16_kernel(const __half* __restrict__ A, const __half* __restrict__ BT,
                      const float* __restrict__ bias, const float* __restrict__ resid,
                      float* __restrict__ Cf, __half* __restrict__ Ch,
                      int M, int N, int K) {
    extern __shared__ char sm[];
    const uint32_t sbase = smem_u32(sm);
    const int tid  = threadIdx.x;
    const int lane = tid & 31;
    const int wid  = tid >> 5;
    const int wm   = wid >> 2;
    const int wn   = wid & 3;
    const int qr   = lane >> 2;
    const int qc   = lane & 3;

    const int rowBase = blockIdx.y * 128;
    const int colBase = blockIdx.x * 128;
    const int NC = K >> 6;

    const int pr = tid >> 3;
    const int pu = tid & 7;

    const int la15  = lane & 15;
    const int ldu   = lane >> 4;
    const int lb_r  = ((lane >> 4) << 3) | (lane & 7);
    const int lb_du = (lane >> 3) & 1;

    float acc[4][4][4];
#pragma unroll
    for (int mf = 0; mf < 4; mf++)
#pragma unroll
        for (int nf = 0; nf < 4; nf++)
#pragma unroll
            for (int r = 0; r < 4; r++) acc[mf][nf][r] = 0.0f;

    auto load_stage = [&](int slot, int chunk) {
        const uint32_t abase = sbase + slot * STAGE_BYTES;
        const uint32_t bbase = abase + TILE_B;
        const int k0 = chunk * 64;
#pragma unroll
        for (int i = 0; i < 4; i++) {
            int r = pr + i * 32;
            int grow = rowBase + r;
            uint32_t dstp = abase + r * 128 + ((pu ^ (r & 7)) << 4);
            const __half* srcp = A + (size_t)grow * K + k0 + pu * 8;
            cp_async16(dstp, srcp, (grow < M) ? 16u : 0u);
        }
#pragma unroll
        for (int i = 0; i < 4; i++) {
            int r = pr + i * 32;
            uint32_t dstp = bbase + r * 128 + ((pu ^ (r & 7)) << 4);
            const __half* srcp = BT + (size_t)(colBase + r) * K + k0 + pu * 8;
            cp_async16(dstp, srcp, 16u);
        }
        CP_COMMIT();
    };

    // prologue: 3 stages in flight
    load_stage(0, 0);
    if (NC > 1) load_stage(1, 1);
    if (NC > 2) load_stage(2, 2);

    uint32_t a[2][4][4];
    uint32_t b[2][4][2];

    auto ld_frags = [&](uint32_t atile, uint32_t btile, int ks, int buf) {
#pragma unroll
        for (int mf = 0; mf < 4; mf++) {
            int r = wm * 64 + mf * 16 + la15;
            uint32_t addr = atile + r * 128 + ((((ks << 1) + ldu) ^ (r & 7)) << 4);
            asm volatile(
                "ldmatrix.sync.aligned.m8n8.x4.shared.b16 {%0,%1,%2,%3}, [%4];"
                : "=r"(a[buf][mf][0]), "=r"(a[buf][mf][1]),
                  "=r"(a[buf][mf][2]), "=r"(a[buf][mf][3])
                : "r"(addr));
        }
#pragma unroll
        for (int nf2 = 0; nf2 < 2; nf2++) {
            int r = wn * 32 + nf2 * 16 + lb_r;
            uint32_t addr = btile + r * 128 + ((((ks << 1) + lb_du) ^ (r & 7)) << 4);
            asm volatile(
                "ldmatrix.sync.aligned.m8n8.x4.shared.b16 {%0,%1,%2,%3}, [%4];"
                : "=r"(b[buf][nf2 * 2][0]), "=r"(b[buf][nf2 * 2][1]),
                  "=r"(b[buf][nf2 * 2 + 1][0]), "=r"(b[buf][nf2 * 2 + 1][1])
                : "r"(addr));
        }
    };

    for (int ci = 0; ci < NC; ci++) {
        CP_WAIT2();
        __syncthreads();          // all warps: chunk ci data visible; slot reuse safe

        int nci = ci + 3;
        if (nci < NC) load_stage(nci & 3, nci);

        const int slot = ci & 3;
        const uint32_t atile = sbase + slot * STAGE_BYTES;
        const uint32_t btile = atile + TILE_B;

        ld_frags(atile, btile, 0, 0);
#pragma unroll
        for (int ks = 0; ks < 4; ks++) {
            const int cur = ks & 1;
            if (ks < 3) ld_frags(atile, btile, ks + 1, cur ^ 1);
#pragma unroll
            for (int mf = 0; mf < 4; mf++)
#pragma unroll
                for (int nf = 0; nf < 4; nf++) {
                    asm volatile(
                        "mma.sync.aligned.m16n8k16.row.col.f32.f16.f16.f32 "
                        "{%0,%1,%2,%3}, {%4,%5,%6,%7}, {%8,%9}, {%0,%1,%2,%3};"
                        : "+f"(acc[mf][nf][0]), "+f"(acc[mf][nf][1]),
                          "+f"(acc[mf][nf][2]), "+f"(acc[mf][nf][3])
                        : "r"(a[cur][mf][0]), "r"(a[cur][mf][1]),
                          "r"(a[cur][mf][2]), "r"(a[cur][mf][3]),
                          "r"(b[cur][nf][0]), "r"(b[cur][nf][1]));
                }
        }
        // no end-of-loop sync: next iteration's barrier orders slot reuse
    }

#pragma unroll
    for (int mf = 0; mf < 4; mf++) {
#pragma unroll
        for (int half = 0; half < 2; half++) {
            int grow = rowBase + wm * 64 + mf * 16 + qr + half * 8;
            if (grow >= M) continue;
#pragma unroll
            for (int nf = 0; nf < 4; nf++) {
                int gcol = colBase + wn * 32 + nf * 8 + 2 * qc;
                float x = acc[mf][nf][half * 2 + 0] + bias[gcol + 0];
                float y = acc[mf][nf][half * 2 + 1] + bias[gcol + 1];
                if (RELU) { x = fmaxf(x, 0.f); y = fmaxf(y, 0.f); }
                if (RESID) {
                    float2 r = *reinterpret_cast<const float2*>(
                        resid + (size_t)grow * N + gcol);
                    x += r.x; y += r.y;
                }
                if (OUT_HALF) {
                    __half2 hv = __floats2half2_rn(x, y);
                    *reinterpret_cast<uint32_t*>(Ch + (size_t)grow * N + gcol) =
                        *reinterpret_cast<uint32_t*>(&hv);
                } else {
                    float2 v; v.x = x; v.y = y;
                    *reinterpret_cast<float2*>(Cf + (size_t)grow * N + gcol) = v;
                }
            }
        }
    }
}

// ---------------------------------------------------------------------------
extern "C" void kernel_launch(void* const* d_in, const int* in_sizes, int n_in,
                              void* d_out, int out_size) {
    const float* feat = (const float*)d_in[0];
    const float* W1   = (const float*)d_in[1];
    const float* b1   = (const float*)d_in[2];
    const float* W2   = (const float*)d_in[3];
    const float* b2   = (const float*)d_in[4];
    const float* eps  = (const float*)d_in[5];
    const int*   src  = (const int*)d_in[6];
    const int*   dst  = (const int*)d_in[7];
    const int n_edges = in_sizes[6];
    float* out = (float*)d_out;

    __half *feath = nullptr, *rsth = nullptr, *h = nullptr, *w1t = nullptr, *w2t = nullptr;
    int *cnt = nullptr, *eidx = nullptr;
    cudaGetSymbolAddress((void**)&feath, g_feat_h);
    cudaGetSymbolAddress((void**)&rsth, g_rst_h);
    cudaGetSymbolAddress((void**)&h, g_h);
    cudaGetSymbolAddress((void**)&w1t, g_w1t);
    cudaGetSymbolAddress((void**)&w2t, g_w2t);
    cudaGetSymbolAddress((void**)&cnt, g_cnt);
    cudaGetSymbolAddress((void**)&eidx, g_eidx);

    cudaFuncSetAttribute(gemm_fp16_kernel<true, false, true>,
                         cudaFuncAttributeMaxDynamicSharedMemorySize, GSM_TOTAL);
    cudaFuncSetAttribute(gemm_fp16_kernel<false, true, false>,
                         cudaFuncAttributeMaxDynamicSharedMemorySize, GSM_TOTAL);

    // 1) fused prep
    prep_kernel<<<NB_PREP, 256>>>(feat, W1, W2, feath, w1t, w2t, cnt);
    // 2) adjacency fill
    {
        int threads_needed = (n_edges + 3) / 4;
        fill_kernel<<<(threads_needed + 255) / 256, 256>>>(src, dst, cnt, eidx, n_edges);
    }
    // 3) fused gather
    {
        int blocks = (N_NODES + 7) / 8;
        gather_kernel<<<blocks, 256>>>(feath, eps, cnt, eidx, rsth);
    }
    // 4) h = fp16(relu(rst @ W1 + b1))
    {
        dim3 grid(D_HID / 128, (N_NODES + 127) / 128);
        gemm_fp16_kernel<true, false, true><<<grid, 256, GSM_TOTAL>>>(
            rsth, w1t, b1, nullptr, nullptr, h, N_NODES, D_HID, D_IN);
    }
    // 5) out = h @ W2 + b2 + feat
    {
        dim3 grid(D_IN / 128, (N_NODES + 127) / 128);
        gemm_fp16_kernel<false, true, false><<<grid, 256, GSM_TOTAL>>>(
            h, w2t, b2, feat, out, nullptr, N_NODES, D_IN, D_HID);
    }
}